// round 16
// baseline (speedup 1.0000x reference)
#include <cuda_runtime.h>
#include <cuda_bf16.h>
#include <math.h>
#include <stdint.h>

#define BATCH     16
#define MEM_DIM   172
#define TOK       4096
#define TIME_DIM  100
#define LEN_TOK   512
#define NROWS     44

// g_wh/g_wl rows: [0,192) = W1 (valid 0-171), [192,384) = W2, [384,512) = Wt (valid 0-99)
#define WROWS     512

__device__ __align__(16) __nv_bfloat16 g_wh[WROWS * TOK];
__device__ __align__(16) __nv_bfloat16 g_wl[WROWS * TOK];
__device__ __align__(16) float g_res[BATCH * NROWS * TOK];

// ---------------------------------------------------------------------------
__device__ __forceinline__ uint32_t s2u(const void* p) {
    return (uint32_t)__cvta_generic_to_shared(p);
}
__device__ __forceinline__ void cp16(uint32_t dst, const void* src) {
    asm volatile("cp.async.cg.shared.global [%0], [%1], 16;" :: "r"(dst), "l"(src));
}
__device__ __forceinline__ void cp_commit() { asm volatile("cp.async.commit_group;"); }
template<int N> __device__ __forceinline__ void cp_wait() {
    asm volatile("cp.async.wait_group %0;" :: "n"(N) : "memory");
}
__device__ __forceinline__ void mma_bf16(float& d0, float& d1, float& d2, float& d3,
                                         uint32_t a0, uint32_t a1, uint32_t a2, uint32_t a3,
                                         uint32_t b0, uint32_t b1)
{
    asm volatile(
        "mma.sync.aligned.m16n8k16.row.col.f32.bf16.bf16.f32 "
        "{%0,%1,%2,%3}, {%4,%5,%6,%7}, {%8,%9}, {%0,%1,%2,%3};"
        : "+f"(d0), "+f"(d1), "+f"(d2), "+f"(d3)
        : "r"(a0), "r"(a1), "r"(a2), "r"(a3), "r"(b0), "r"(b1));
}
__device__ __forceinline__ void ldsm_x4(uint32_t& r0, uint32_t& r1, uint32_t& r2,
                                        uint32_t& r3, uint32_t addr) {
    asm volatile("ldmatrix.sync.aligned.m8n8.x4.shared.b16 {%0,%1,%2,%3}, [%4];"
                 : "=r"(r0), "=r"(r1), "=r"(r2), "=r"(r3) : "r"(addr));
}
__device__ __forceinline__ void ldsm_x2t(uint32_t& r0, uint32_t& r1, uint32_t addr) {
    asm volatile("ldmatrix.sync.aligned.m8n8.x2.trans.shared.b16 {%0,%1}, [%2];"
                 : "=r"(r0), "=r"(r1) : "r"(addr));
}

// ---------------------------------------------------------------------------
// Prep: split W1/W2/Wt into bf16 hi/lo. 8 elements per thread.
// ---------------------------------------------------------------------------
__global__ void __launch_bounds__(256)
k_prep(const float* __restrict__ W1, const float* __restrict__ W2,
       const float* __restrict__ Wt)
{
    int i = blockIdx.x * 256 + threadIdx.x;          // one per 8-col group
    if (i >= WROWS * (TOK / 8)) return;
    int row = i >> 9;                                // 512 groups per row
    int c8  = (i & 511) << 3;

    const float* src = nullptr;
    if (row < 192)      { if (row < 172)            src = W1 + (size_t)row * TOK + c8; }
    else if (row < 384) { int k = row - 192; if (k < 172) src = W2 + (size_t)k * TOK + c8; }
    else                { int k = row - 384; if (k < 100) src = Wt + (size_t)k * TOK + c8; }

    float v[8] = {0.f, 0.f, 0.f, 0.f, 0.f, 0.f, 0.f, 0.f};
    if (src) {
        float4 a = __ldg((const float4*)src);
        float4 b = __ldg((const float4*)(src + 4));
        v[0] = a.x; v[1] = a.y; v[2] = a.z; v[3] = a.w;
        v[4] = b.x; v[5] = b.y; v[6] = b.z; v[7] = b.w;
    }
    __align__(16) __nv_bfloat16 h[8], l[8];
#pragma unroll
    for (int j = 0; j < 8; j++) {
        h[j] = __float2bfloat16(v[j]);
        l[j] = __float2bfloat16(v[j] - __bfloat162float(h[j]));
    }
    *(uint4*)(g_wh + (size_t)row * TOK + c8) = *(uint4*)h;
    *(uint4*)(g_wl + (size_t)row * TOK + c8) = *(uint4*)l;
}

// ---------------------------------------------------------------------------
// Proj smem layout (bytes):
//   A region [0, 25600):
//     G1/G2: A1h@0, A1l@6400, A2h@12800, A2l@19200 (16 rows x 200 cols bf16, 400B rows)
//     G3 (reuse): Th@0, Tl@8704 (32 rows x 136 cols bf16, 272B rows)
//   2 W stages @25600: each = [hi 32x528B][lo 32x528B] = 33792 B
// ---------------------------------------------------------------------------
#define A_REGION_B 25600
#define WS_ROW_B   528
#define WSTG_B     (2 * 32 * WS_ROW_B)               // 33792
#define SMEMP_B    (A_REGION_B + 2 * WSTG_B)         // 93184 -> 2 CTAs/SM

#define NTHREADS   512                               // 16 warps, 16 cols/warp

// Fill one K=32 stage: 32 rows x 256 cols, hi + lo. 2048 cp16 / 512 thr = 4 each.
__device__ __forceinline__ void fill_wstage(char* stg, int krow0, int col0, int tid)
{
#pragma unroll
    for (int j = 0; j < 4; j++) {
        int c   = tid + NTHREADS * j;       // 0..2047
        int mat = c >> 10;                  // 0 = hi, 1 = lo
        int r   = (c >> 5) & 31;
        int c16 = c & 31;
        const __nv_bfloat16* src = (mat ? g_wl : g_wh)
                                 + (size_t)(krow0 + r) * TOK + col0 + c16 * 8;
        cp16(s2u(stg + mat * (32 * WS_ROW_B) + r * WS_ROW_B + c16 * 16), src);
    }
}

// One GEMM: MT m16-tiles, NSTEP k32-steps, double-buffered cp.async pipeline.
// 16 warps, each owning 16 output columns (2 n8-tiles). 3-product bf16 comp.
template<int MT, int NSTEP>
__device__ __forceinline__ void run_gemm(
    char* s0, char* s1,
    uint32_t aH, uint32_t aL, int astride_b,
    int wrow0, int col0, int b, int orow0, int nvalid,
    const float* __restrict__ bias, int tid)
{
    const int lane = tid & 31;
    const int wid  = tid >> 5;              // 0..15
    const int n0   = wid * 16;
    const int g    = lane >> 2;
    const int tg   = lane & 3;
    const int arow = lane & 15;
    const int acol = (lane >> 4) << 3;
    const int brow = lane & 15;

    float acc[MT][2][4];
#pragma unroll
    for (int mt = 0; mt < MT; mt++)
#pragma unroll
        for (int j = 0; j < 2; j++)
#pragma unroll
            for (int q = 0; q < 4; q++) acc[mt][j][q] = 0.f;

    fill_wstage(s0, wrow0, col0, tid);
    cp_commit();

    for (int s = 0; s < NSTEP; s++) {
        if (s + 1 < NSTEP) {
            fill_wstage((s & 1) ? s0 : s1, wrow0 + (s + 1) * 32, col0, tid);
            cp_commit();
            cp_wait<1>();
        } else {
            cp_wait<0>();
        }
        __syncthreads();

        char* st = (s & 1) ? s1 : s0;
        const uint32_t st_s = s2u(st);

#pragma unroll
        for (int kc = 0; kc < 2; kc++) {
            const int k0 = s * 32 + kc * 16;

            uint32_t bh[2][2], bl[2][2];
#pragma unroll
            for (int j = 0; j < 2; j++) {
                uint32_t baddr = st_s + (kc * 16 + brow) * WS_ROW_B + (n0 + j * 8) * 2;
                ldsm_x2t(bh[j][0], bh[j][1], baddr);
                ldsm_x2t(bl[j][0], bl[j][1], baddr + 32 * WS_ROW_B);
            }
#pragma unroll
            for (int mt = 0; mt < MT; mt++) {
                uint32_t ah0, ah1, ah2, ah3, al0, al1, al2, al3;
                ldsm_x4(ah0, ah1, ah2, ah3,
                        aH + (mt * 16 + arow) * astride_b + (k0 + acol) * 2);
                ldsm_x4(al0, al1, al2, al3,
                        aL + (mt * 16 + arow) * astride_b + (k0 + acol) * 2);
#pragma unroll
                for (int j = 0; j < 2; j++) {
                    mma_bf16(acc[mt][j][0], acc[mt][j][1], acc[mt][j][2], acc[mt][j][3],
                             ah0, ah1, ah2, ah3, bh[j][0], bh[j][1]);
                    mma_bf16(acc[mt][j][0], acc[mt][j][1], acc[mt][j][2], acc[mt][j][3],
                             ah0, ah1, ah2, ah3, bl[j][0], bl[j][1]);
                    mma_bf16(acc[mt][j][0], acc[mt][j][1], acc[mt][j][2], acc[mt][j][3],
                             al0, al1, al2, al3, bh[j][0], bh[j][1]);
                }
            }
        }
        __syncthreads();
    }

    // writeback with bias
    float* base = g_res + ((size_t)b * NROWS + orow0) * TOK + col0;
#pragma unroll
    for (int mt = 0; mt < MT; mt++) {
        const int r0 = mt * 16 + g;
#pragma unroll
        for (int j = 0; j < 2; j++) {
            const int c = n0 + j * 8 + tg * 2;
            float bv0 = __ldg(&bias[col0 + c]);
            float bv1 = __ldg(&bias[col0 + c + 1]);
            if (r0 < nvalid) {
                float2 v = make_float2(acc[mt][j][0] + bv0, acc[mt][j][1] + bv1);
                *(float2*)(base + (size_t)r0 * TOK + c) = v;
            }
            if (r0 + 8 < nvalid) {
                float2 v = make_float2(acc[mt][j][2] + bv0, acc[mt][j][3] + bv1);
                *(float2*)(base + (size_t)(r0 + 8) * TOK + c) = v;
            }
        }
    }
}

// ---------------------------------------------------------------------------
// Proj: grid (16 batches, 16 n-tiles of 256 cols) = 256 CTAs, block 512.
// ---------------------------------------------------------------------------
__global__ void __launch_bounds__(NTHREADS)
k_proj(const float* __restrict__ memory,
       const int*   __restrict__ src_nodes,
       const int*   __restrict__ dst_nodes,
       const int*   __restrict__ src_nei,
       const int*   __restrict__ dst_nei,
       const float* __restrict__ timestamps,
       const float* __restrict__ se,
       const float* __restrict__ de,
       const float* __restrict__ b1,
       const float* __restrict__ b2,
       const float* __restrict__ bt,
       const float* __restrict__ w_time,
       const float* __restrict__ phase)
{
    extern __shared__ __align__(16) char sm[];
    char* Areg = sm;
    char* s0 = sm + A_REGION_B;
    char* s1 = s0 + WSTG_B;

    const int b    = blockIdx.x;
    const int tile = blockIdx.y;
    const int col0 = tile * 256;
    const int tid  = threadIdx.x;

    // ---- stage A1/A2 hi/lo (16 rows x 200 cols each; valid r<11, k<172) ----
    for (int i = tid; i < 2 * 16 * 200; i += NTHREADS) {
        int m = i / (16 * 200);
        int r = (i / 200) & 15;
        int k = i % 200;
        float a = 0.f;
        if (r < 11 && k < 172) {
            int node;
            if (m == 0) node = (r == 0) ? src_nodes[b] : dst_nei[b * 10 + r - 1];
            else        node = (r == 0) ? dst_nodes[b] : src_nei[b * 10 + r - 1];
            a = memory[(size_t)node * MEM_DIM + k];
        }
        __nv_bfloat16 h = __float2bfloat16(a);
        __nv_bfloat16 l = __float2bfloat16(a - __bfloat162float(h));
        __nv_bfloat16* Ah = (__nv_bfloat16*)(Areg + m * 12800);
        __nv_bfloat16* Al = (__nv_bfloat16*)(Areg + m * 12800 + 6400);
        Ah[r * 200 + k] = h;
        Al[r * 200 + k] = l;
    }
    // (sync provided by first in-loop barrier of G1)

    const uint32_t A1h = s2u(Areg), A1l = s2u(Areg + 6400);
    const uint32_t A2h = s2u(Areg + 12800), A2l = s2u(Areg + 19200);

    run_gemm<1, 6>(s0, s1, A1h, A1l, 400, 0,   col0, b, 0,  11, b1, tid);
    run_gemm<1, 6>(s0, s1, A2h, A2l, 400, 192, col0, b, 11, 11, b2, tid);

    // ---- stage tenc hi/lo (32 rows x 136 cols; valid r<21, k<100) ----
    __syncthreads();
    const float t0 = timestamps[b];
    for (int i = tid; i < 32 * 136; i += NTHREADS) {
        int r = i / 136;
        int k = i % 136;
        float v = 0.f;
        if (r < 21 && k < 100) {
            float delta;
            if (r == 0)      delta = 0.f;
            else if (r < 11) delta = t0 - se[b * 10 + r - 1];
            else             delta = t0 - de[b * 10 + r - 11];
            v = cosf(delta * w_time[k] + phase[k]);
        }
        __nv_bfloat16 h = __float2bfloat16(v);
        __nv_bfloat16 l = __float2bfloat16(v - __bfloat162float(h));
        ((__nv_bfloat16*)Areg)[r * 136 + k] = h;
        ((__nv_bfloat16*)(Areg + 8704))[r * 136 + k] = l;
    }

    const uint32_t Th = s2u(Areg), Tl = s2u(Areg + 8704);
    run_gemm<2, 4>(s0, s1, Th, Tl, 272, 384, col0, b, 22, 21, bt, tid);
}

// ---------------------------------------------------------------------------
// Scat (proven): grid (16 b, 16 tiles of 256 cols, 25 runs), block 256.
// ---------------------------------------------------------------------------
__global__ void __launch_bounds__(256)
k_scat(float* __restrict__ out)
{
    const int b    = blockIdx.x;
    const int tile = blockIdx.y;
    const int z    = blockIdx.z;
    const int tid  = threadIdx.x;
    const int lane = tid & 63;
    const int sub  = tid >> 6;

    int t0, n, rS, rD, rT;
    if (z < 10)       { t0 = 15 + 21 * z;  n = 21; rS = 0;  rD = 12 + z; rT = 23 + z; }
    else if (z < 20)  { int q = z - 10; t0 = 239 + 21 * q; n = 21; rS = 11; rD = 1 + q; rT = 33 + q; }
    else if (z == 20) { t0 = 0;   n = 15; rS = 0;  rD = 11; rT = 22; }
    else if (z == 21) { t0 = 225; n = 14; rS = 11; rD = 11; rT = 22; }
    else              { t0 = 449 + 21 * (z - 22); n = 21; rS = 0; rD = 11; rT = 22; }

    const float4* gresv = (const float4*)g_res;
    const int vrow = TOK / 4;
    const size_t rbase = (size_t)b * NROWS * vrow + tile * 64 + lane;
    const float4 vs = __ldg(&gresv[rbase + (size_t)rS * vrow]);
    const float4 vd = __ldg(&gresv[rbase + (size_t)rD * vrow]);
    const float4 vt = __ldg(&gresv[rbase + (size_t)rT * vrow]);

    float4* outv = (float4*)out;
    const size_t T = (size_t)BATCH * LEN_TOK * vrow;
    const size_t obase = (size_t)(b * LEN_TOK) * vrow + tile * 64 + lane;

    if (z == 20) {
        for (int i = sub; i < n; i += 4) {
            const int t = t0 + i;
            const size_t o = obase + (size_t)t * vrow;
            __stcs(&outv[o],         vs);
            __stcs(&outv[o + T],     (t == 0) ? vd : vs);
            __stcs(&outv[o + 2 * T], vt);
        }
    } else {
        for (int i = sub; i < n; i += 4) {
            const size_t o = obase + (size_t)(t0 + i) * vrow;
            __stcs(&outv[o],         vs);
            __stcs(&outv[o + T],     vd);
            __stcs(&outv[o + 2 * T], vt);
        }
    }
}

// ---------------------------------------------------------------------------
extern "C" void kernel_launch(void* const* d_in, const int* in_sizes, int n_in,
                              void* d_out, int out_size)
{
    const float* memory      = (const float*)d_in[0];
    const int*   src_nodes   = (const int*)  d_in[1];
    const int*   dst_nodes   = (const int*)  d_in[2];
    const int*   src_nei     = (const int*)  d_in[3];
    const int*   dst_nei     = (const int*)  d_in[4];
    const float* timestamps  = (const float*)d_in[5];
    const float* se          = (const float*)d_in[6];
    const float* de          = (const float*)d_in[7];
    const float* W1          = (const float*)d_in[8];
    const float* b1          = (const float*)d_in[9];
    const float* W2          = (const float*)d_in[10];
    const float* b2          = (const float*)d_in[11];
    const float* Wt          = (const float*)d_in[12];
    const float* bt          = (const float*)d_in[13];
    const float* w_time      = (const float*)d_in[14];
    const float* phase       = (const float*)d_in[15];
    float* out = (float*)d_out;

    cudaFuncSetAttribute(k_proj, cudaFuncAttributeMaxDynamicSharedMemorySize, SMEMP_B);

    k_prep<<<(WROWS * (TOK / 8) + 255) / 256, 256>>>(W1, W2, Wt);
    k_proj<<<dim3(BATCH, TOK / 256), NTHREADS, SMEMP_B>>>(memory, src_nodes, dst_nodes,
                                                          src_nei, dst_nei,
                                                          timestamps, se, de,
                                                          b1, b2, bt, w_time, phase);
    k_scat<<<dim3(BATCH, TOK / 256, 25), 256>>>(out);
}